// round 1
// baseline (speedup 1.0000x reference)
#include <cuda_runtime.h>
#include <cuda_bf16.h>
#include <cstdint>

#define ULL unsigned long long

// ---------------- device globals (scratch; no allocation allowed) -------------
// U transposed: g_Ut[j*256 + i] = <i| C_fixed |j>  (column j contiguous)
__device__ float2 g_Ut[256 * 256];          // 512 KB
__device__ float2 g_cs[8192 * 8];           // (c,s) per (batch, wire), 512 KB

// ---------------- helpers -----------------------------------------------------
__device__ __forceinline__ float2 cmul(float2 a, float2 b) {
    return make_float2(a.x * b.x - a.y * b.y, a.x * b.y + a.y * b.x);
}
__device__ __forceinline__ float2 cadd(float2 a, float2 b) {
    return make_float2(a.x + b.x, a.y + b.y);
}
__device__ __forceinline__ ULL pack2(float lo, float hi) {
    ULL r; asm("mov.b64 %0, {%1, %2};" : "=l"(r) : "f"(lo), "f"(hi)); return r;
}
__device__ __forceinline__ void unpack2(ULL v, float& lo, float& hi) {
    asm("mov.b64 {%0, %1}, %2;" : "=f"(lo), "=f"(hi) : "l"(v));
}
// packed f32x2 FMA: acc.{lo,hi} += u.{lo,hi} * s.{lo,hi}
__device__ __forceinline__ void ffma2(ULL& a, ULL u, ULL s) {
    asm("fma.rn.f32x2 %0, %1, %2, %0;" : "+l"(a) : "l"(u), "l"(s));
}
__device__ __forceinline__ void cp16(void* smem_dst, const void* gsrc) {
    unsigned sa = (unsigned)__cvta_generic_to_shared(smem_dst);
    asm volatile("cp.async.cg.shared.global [%0], [%1], 16;" :: "r"(sa), "l"(gsrc));
}
__device__ __forceinline__ void cp_commit() { asm volatile("cp.async.commit_group;"); }
__device__ __forceinline__ void cp_wait0()  { asm volatile("cp.async.wait_group 0;"); }

// ---------------- K1: build fixed 256x256 unitary -----------------------------
// 256 blocks (one per basis-state column) x 128 threads; state in shared.
__global__ void build_unitary(const float* __restrict__ qw) {
    __shared__ float2 st[256];
    const int j = blockIdx.x;
    const int t = threadIdx.x;
    st[t]       = make_float2(t == j ? 1.f : 0.f, 0.f);
    st[t + 128] = make_float2((t + 128) == j ? 1.f : 0.f, 0.f);

    for (int l = 0; l < 3; l++) {
        // Rot on each wire: RZ(omega) RY(theta) RZ(phi)
        for (int w = 0; w < 8; w++) {
            const float phi = qw[(l * 8 + w) * 3 + 0];
            const float th  = qw[(l * 8 + w) * 3 + 1];
            const float om  = qw[(l * 8 + w) * 3 + 2];
            float ct, stn;  __sincosf(0.5f * th, &stn, &ct);
            ct = cosf(0.5f * th); stn = sinf(0.5f * th);   // full precision
            float s1, c1, s2, c2;
            sincosf(0.5f * (phi + om), &s1, &c1);
            sincosf(0.5f * (phi - om), &s2, &c2);
            const float2 u00 = make_float2( c1 * ct, -s1 * ct);
            const float2 u01 = make_float2(-c2 * stn, -s2 * stn);
            const float2 u10 = make_float2( c2 * stn, -s2 * stn);
            const float2 u11 = make_float2( c1 * ct,  s1 * ct);

            const int m  = 1 << (7 - w);
            const int lo = t & (m - 1);
            const int i0 = ((t - lo) << 1) | lo;
            const int i1 = i0 | m;
            __syncthreads();
            const float2 a = st[i0], b = st[i1];
            st[i0] = cadd(cmul(u00, a), cmul(u01, b));
            st[i1] = cadd(cmul(u10, a), cmul(u11, b));
        }
        // CNOT ring with range r = l+1 (l < 7)
        const int r = l + 1;
        for (int w = 0; w < 8; w++) {
            const int cm = 1 << (7 - w);
            const int tm = 1 << (7 - ((w + r) & 7));
            __syncthreads();
            for (int i = t; i < 256; i += 128) {
                if ((i & cm) && !(i & tm)) {
                    float2 tmp = st[i]; st[i] = st[i | tm]; st[i | tm] = tmp;
                }
            }
        }
    }
    __syncthreads();
    g_Ut[j * 256 + t]       = st[t];
    g_Ut[j * 256 + t + 128] = st[t + 128];
}

// ---------------- K2: projection + sigmoid -> (cos(a/2), sin(a/2)) ------------
// 1024 blocks x 256 threads; one warp per batch element.
__global__ void angles_kernel(const float* __restrict__ x,
                              const float* __restrict__ W,
                              const float* __restrict__ bvec,
                              const float* __restrict__ scale,
                              const float* __restrict__ bias) {
    __shared__ float4 W4[8 * 128];   // 16 KB: W as 8 rows x 128 float4
    const int t = threadIdx.x;
    for (int e = t; e < 1024; e += 256) W4[e] = ((const float4*)W)[e];
    __syncthreads();

    const int warp = t >> 5, lane = t & 31;
    const int b = blockIdx.x * 8 + warp;
    const float4* x4 = (const float4*)(x + (size_t)b * 512);

    float acc[8] = {0, 0, 0, 0, 0, 0, 0, 0};
#pragma unroll
    for (int q = 0; q < 4; q++) {
        const float4 xv = x4[lane + 32 * q];
#pragma unroll
        for (int w = 0; w < 8; w++) {
            const float4 wv = W4[w * 128 + lane + 32 * q];
            acc[w] += xv.x * wv.x + xv.y * wv.y + xv.z * wv.z + xv.w * wv.w;
        }
    }
#pragma unroll
    for (int off = 16; off; off >>= 1)
#pragma unroll
        for (int w = 0; w < 8; w++)
            acc[w] += __shfl_xor_sync(0xffffffffu, acc[w], off);

    if (lane == 0) {
#pragma unroll
        for (int w = 0; w < 8; w++) {
            const float p = acc[w] + bvec[w];
            const float a = (1.f / (1.f + expf(-(p * scale[w] + bias[w])))) * 3.14159265358979323846f;
            float s, c; sincosf(0.5f * a, &s, &c);
            g_cs[b * 8 + w] = make_float2(c, s);
        }
    }
}

// ---------------- K3: product state -> y = U psi -> <Z_w> ----------------------
// 128 blocks x 512 threads, 64 batch elements per block.
// Dynamic smem: csh(4KB) | Ps 256x64 f32 (64KB) | Us 2x16x256 float2 (64KB) | sOut(2KB)
#define K3_SMEM (4096 + 65536 + 65536 + 2048)

__global__ void __launch_bounds__(512, 1) qc_main(float* __restrict__ out) {
    extern __shared__ char smem[];
    float2* csh = (float2*)smem;                         // [64][8]
    float*  Ps  = (float*)(smem + 4096);                 // [256][64]
    ULL*    Us  = (ULL*)(smem + 4096 + 65536);           // [2][16][256] (float2 as ull)
    float*  sOut = (float*)(smem + 4096 + 131072);       // [8][64]

    const int t  = threadIdx.x;
    const int b0 = blockIdx.x * 64;

    if (t < 512) sOut[t] = 0.f;   // 8*64 = 512, one each
    if (t < 512) csh[t] = g_cs[b0 * 8 + t];
    __syncthreads();

    // build product-state tile Ps[j][b]
    {
        const int j = t & 255;
        const int bh = (t >> 8) * 32;
        for (int b = bh; b < bh + 32; b++) {
            float v = 1.f;
#pragma unroll
            for (int w = 0; w < 8; w++) {
                const float2 cw = csh[b * 8 + w];
                v *= ((j >> (7 - w)) & 1) ? cw.y : cw.x;
            }
            Ps[j * 64 + b] = v;
        }
    }

    // prologue: chunk 0 of U into buffer 0 (each chunk = 16 j-rows = 32KB = 2048 float4)
    const float4* Ug = (const float4*)g_Ut;
    {
        float4* dst = (float4*)Us;
#pragma unroll
        for (int q = 0; q < 4; q++) cp16(&dst[t + 512 * q], &Ug[t + 512 * q]);
        cp_commit(); cp_wait0();
    }
    __syncthreads();

    const int ibase = (t >> 4) * 8;      // 32 i-groups of 8
    const int bbase = (t & 15) * 4;      // 16 b-groups of 4

    ULL acc[32];
#pragma unroll
    for (int k = 0; k < 32; k++) acc[k] = 0;

    for (int c = 0; c < 16; c++) {
        if (c < 15) {  // async-prefetch next chunk into the other buffer
            float4* dst = (float4*)(Us + ((c + 1) & 1) * 4096);
            const float4* src = &Ug[(c + 1) * 2048];
#pragma unroll
            for (int q = 0; q < 4; q++) cp16(&dst[t + 512 * q], &src[t + 512 * q]);
            cp_commit();
        }
        const ULL* Ub = Us + (c & 1) * 4096;
#pragma unroll 4
        for (int jj = 0; jj < 16; jj++) {
            const ULL* up = Ub + jj * 256 + ibase;
            ULL u[8];
#pragma unroll
            for (int ii = 0; ii < 8; ii++) u[ii] = up[ii];
            const float4 pv = *(const float4*)(Ps + (c * 16 + jj) * 64 + bbase);
            ULL s[4];
            s[0] = pack2(pv.x, pv.x); s[1] = pack2(pv.y, pv.y);
            s[2] = pack2(pv.z, pv.z); s[3] = pack2(pv.w, pv.w);
#pragma unroll
            for (int ii = 0; ii < 8; ii++)
#pragma unroll
                for (int bb = 0; bb < 4; bb++)
                    ffma2(acc[ii * 4 + bb], u[ii], s[bb]);
        }
        if (c < 15) cp_wait0();
        __syncthreads();
    }

    // epilogue: probabilities -> signed sums into sOut[w][b]
#pragma unroll
    for (int bb = 0; bb < 4; bb++) {
        float z[8] = {0, 0, 0, 0, 0, 0, 0, 0};
#pragma unroll
        for (int ii = 0; ii < 8; ii++) {
            float re, im; unpack2(acc[ii * 4 + bb], re, im);
            const float p = re * re + im * im;
            const int i = ibase + ii;
#pragma unroll
            for (int w = 0; w < 8; w++)
                z[w] += (i & (1 << (7 - w))) ? -p : p;
        }
#pragma unroll
        for (int w = 0; w < 8; w++)
            atomicAdd(&sOut[w * 64 + bbase + bb], z[w]);
    }
    __syncthreads();

    if (t < 512) {
        const int b = t >> 3, w = t & 7;
        out[(size_t)(b0 + b) * 8 + w] = sOut[w * 64 + b];
    }
}

// ---------------- launch -------------------------------------------------------
extern "C" void kernel_launch(void* const* d_in, const int* in_sizes, int n_in,
                              void* d_out, int out_size) {
    (void)in_sizes; (void)n_in; (void)out_size;
    const float* x     = (const float*)d_in[0];
    const float* W     = (const float*)d_in[1];
    const float* bvec  = (const float*)d_in[2];
    const float* scale = (const float*)d_in[3];
    const float* bias  = (const float*)d_in[4];
    const float* qw    = (const float*)d_in[5];
    float* out = (float*)d_out;

    cudaFuncSetAttribute(qc_main, cudaFuncAttributeMaxDynamicSharedMemorySize, K3_SMEM);

    build_unitary<<<256, 128>>>(qw);
    angles_kernel<<<1024, 256>>>(x, W, bvec, scale, bias);
    qc_main<<<128, 512, K3_SMEM>>>(out);
}

// round 3
// speedup vs baseline: 1.7628x; 1.7628x over previous
#include <cuda_runtime.h>
#include <cuda_fp16.h>
#include <cstdint>

// ===================== device staging (no allocation allowed) =================
// B^T layout: g_Bt[n][k], n = 2i (re) / 2i+1 (im), k in [0,256)=Uh, [256,512)=Uh,
// [512,768)=Ul.  768 KB (L2-resident).
__device__ __half g_Bt[512][768];
// A layout: g_Ah[b][k], k in [0,256)=psi_h, [256,512)=psi_l, [512,768)=psi_h.
__device__ __half g_Ah[8192][768];

// ===================== PTX helpers ===========================================
__device__ __forceinline__ uint32_t smem_u32(const void* p) {
    uint32_t a;
    asm("{ .reg .u64 t; cvta.to.shared.u64 t, %1; cvt.u32.u64 %0, t; }" : "=r"(a) : "l"(p));
    return a;
}
__device__ __forceinline__ void cp16s(uint32_t sa, const void* g) {
    asm volatile("cp.async.cg.shared.global [%0], [%1], 16;" :: "r"(sa), "l"(g));
}
__device__ __forceinline__ void cp_commit() { asm volatile("cp.async.commit_group;" ::: "memory"); }
__device__ __forceinline__ void cp_wait0()  { asm volatile("cp.async.wait_group 0;" ::: "memory"); }
__device__ __forceinline__ void cp_wait1()  { asm volatile("cp.async.wait_group 1;" ::: "memory"); }

#define LDSM4(r, addr) \
    asm volatile("ldmatrix.sync.aligned.m8n8.x4.shared.b16 {%0,%1,%2,%3}, [%4];" \
                 : "=r"((r)[0]), "=r"((r)[1]), "=r"((r)[2]), "=r"((r)[3]) : "r"(addr))

#define MMA16816(d, a, b0, b1) \
    asm volatile("mma.sync.aligned.m16n8k16.row.col.f32.f16.f16.f32 " \
                 "{%0,%1,%2,%3}, {%4,%5,%6,%7}, {%8,%9}, {%0,%1,%2,%3};" \
                 : "+f"((d)[0]), "+f"((d)[1]), "+f"((d)[2]), "+f"((d)[3]) \
                 : "r"((a)[0]), "r"((a)[1]), "r"((a)[2]), "r"((a)[3]), "r"(b0), "r"(b1))

// ===================== K1: build U, fp16 split -> g_Bt =======================
__device__ __forceinline__ float2 cmulf(float2 a, float2 b) {
    return make_float2(a.x * b.x - a.y * b.y, a.x * b.y + a.y * b.x);
}
__global__ void build_unitary(const float* __restrict__ qw) {
    __shared__ float2 stA[256], stB[256];
    __shared__ float2 gsh[24][4];
    const int j = blockIdx.x, t = threadIdx.x;   // 128 threads

    if (t < 24) {
        const float phi = qw[t * 3 + 0], th = qw[t * 3 + 1], om = qw[t * 3 + 2];
        float ct, stn; sincosf(0.5f * th, &stn, &ct);
        float s1, c1, s2, c2;
        sincosf(0.5f * (phi + om), &s1, &c1);
        sincosf(0.5f * (phi - om), &s2, &c2);
        gsh[t][0] = make_float2( c1 * ct,  -s1 * ct);
        gsh[t][1] = make_float2(-c2 * stn, -s2 * stn);
        gsh[t][2] = make_float2( c2 * stn, -s2 * stn);
        gsh[t][3] = make_float2( c1 * ct,   s1 * ct);
    }
    stA[t]       = make_float2(t == j ? 1.f : 0.f, 0.f);
    stA[t + 128] = make_float2((t + 128) == j ? 1.f : 0.f, 0.f);

    float2* cur = stA; float2* nxt = stB;
    for (int l = 0; l < 3; l++) {
        for (int w = 0; w < 8; w++) {
            __syncthreads();
            const int g = l * 8 + w;
            const int m = 1 << (7 - w);
            const int lo = t & (m - 1);
            const int i0 = ((t - lo) << 1) | lo;
            const int i1 = i0 | m;
            const float2 a = cur[i0], b = cur[i1];
            const float2 r0 = cmulf(gsh[g][0], a), r1 = cmulf(gsh[g][1], b);
            const float2 r2 = cmulf(gsh[g][2], a), r3 = cmulf(gsh[g][3], b);
            cur[i0] = make_float2(r0.x + r1.x, r0.y + r1.y);
            cur[i1] = make_float2(r2.x + r3.x, r2.y + r3.y);
        }
        __syncthreads();
        const int r = l + 1;
#pragma unroll
        for (int h = 0; h < 2; h++) {
            const int i = t + h * 128;
            int idx = i;
#pragma unroll
            for (int w = 0; w < 8; w++) {
                const int cm = 1 << (7 - w);
                const int tm = 1 << (7 - ((w + r) & 7));
                if (idx & cm) idx ^= tm;
            }
            nxt[idx] = cur[i];
        }
        float2* tmp = cur; cur = nxt; nxt = tmp;
    }
    __syncthreads();

#pragma unroll
    for (int h = 0; h < 2; h++) {
        const int i = t + h * 128;
        const float2 v = cur[i];
        const __half hre = __float2half_rn(v.x);
        const __half lre = __float2half_rn(v.x - __half2float(hre));
        const __half him = __float2half_rn(v.y);
        const __half lim = __float2half_rn(v.y - __half2float(him));
        g_Bt[2 * i][j]           = hre;
        g_Bt[2 * i][j + 256]     = hre;
        g_Bt[2 * i][j + 512]     = lre;
        g_Bt[2 * i + 1][j]       = him;
        g_Bt[2 * i + 1][j + 256] = him;
        g_Bt[2 * i + 1][j + 512] = lim;
    }
}

// ===================== K2: projection + angles -> g_Ah =======================
__global__ void psi_kernel(const float* __restrict__ x, const float* __restrict__ W,
                           const float* __restrict__ bvec, const float* __restrict__ scale,
                           const float* __restrict__ bias) {
    __shared__ float4 W4[1024];
    const int t = threadIdx.x;
    for (int e = t; e < 1024; e += 256) W4[e] = ((const float4*)W)[e];
    __syncthreads();

    const int warp = t >> 5, lane = t & 31;
    const int b = blockIdx.x * 8 + warp;
    const float4* x4 = (const float4*)(x + (size_t)b * 512);

    float acc[8] = {0, 0, 0, 0, 0, 0, 0, 0};
#pragma unroll
    for (int q = 0; q < 4; q++) {
        const float4 xv = x4[lane + 32 * q];
#pragma unroll
        for (int w = 0; w < 8; w++) {
            const float4 wv = W4[w * 128 + lane + 32 * q];
            acc[w] += xv.x * wv.x + xv.y * wv.y + xv.z * wv.z + xv.w * wv.w;
        }
    }
#pragma unroll
    for (int off = 16; off; off >>= 1)
#pragma unroll
        for (int w = 0; w < 8; w++)
            acc[w] += __shfl_xor_sync(0xffffffffu, acc[w], off);

    float cw = 0.f, sw_ = 0.f;
    if (lane < 8) {
        const float p = acc[lane] + bvec[lane];
        const float a = (1.f / (1.f + expf(-(p * scale[lane] + bias[lane])))) *
                        3.14159265358979323846f;
        sincosf(0.5f * a, &sw_, &cw);
    }
    float c[8], s[8];
#pragma unroll
    for (int w = 0; w < 8; w++) {
        c[w] = __shfl_sync(0xffffffffu, cw, w);
        s[w] = __shfl_sync(0xffffffffu, sw_, w);
    }

    float base = ((lane & 16) ? s[0] : c[0]);
    base *= ((lane & 8) ? s[1] : c[1]);
    base *= ((lane & 4) ? s[2] : c[2]);
    base *= ((lane & 2) ? s[3] : c[3]);
    base *= ((lane & 1) ? s[4] : c[4]);

    uint32_t hv[4], lv[4];
#pragma unroll
    for (int qp = 0; qp < 4; qp++) {
        uint32_t hp = 0, lp = 0;
#pragma unroll
        for (int half_ = 0; half_ < 2; half_++) {
            const int q = qp * 2 + half_;
            const float T = ((q & 4) ? s[5] : c[5]) * ((q & 2) ? s[6] : c[6]) *
                            ((q & 1) ? s[7] : c[7]);
            const float v = base * T;
            const __half hh = __float2half_rn(v);
            const __half hl = __float2half_rn(v - __half2float(hh));
            hp |= ((uint32_t)__half_as_ushort(hh)) << (16 * half_);
            lp |= ((uint32_t)__half_as_ushort(hl)) << (16 * half_);
        }
        hv[qp] = hp; lv[qp] = lp;
    }

    uint4* row = (uint4*)&g_Ah[b][0];
    row[lane]      = make_uint4(hv[0], hv[1], hv[2], hv[3]);   // psi_h at k=lane*8
    row[lane + 32] = make_uint4(lv[0], lv[1], lv[2], lv[3]);   // psi_l at 256+
    row[lane + 64] = make_uint4(hv[0], hv[1], hv[2], hv[3]);   // psi_h at 512+
}

// ===================== K3: HMMA GEMM + expval epilogue =======================
// 128 blocks x 512 threads (16 warps: wm in {0,1} x wn in 0..7).
// Warp tile M=32, N=64. Stage: A 64x72 halfs (9216B) + B 512x72 halfs (73728B).
#define STAGE  82944
#define QC_SMEM (2 * STAGE)

__device__ __forceinline__ void stage_copy(uint32_t sb, int c, int buf, int t,
                                           const __half* gA) {
    const uint32_t st = sb + (uint32_t)buf * STAGE;
    const int r = t >> 3, off = (t & 7) * 8;
    cp16s(st + (r * 72 + off) * 2, gA + r * 768 + c * 64 + off);
#pragma unroll
    for (int p = 0; p < 8; p++) {
        const int n = p * 64 + r;
        cp16s(st + 9216 + (n * 72 + off) * 2, &g_Bt[n][c * 64 + off]);
    }
    cp_commit();
}

__global__ void __launch_bounds__(512) qc_main(float* __restrict__ out) {
    extern __shared__ __align__(128) char smem[];
    const uint32_t sb = smem_u32(smem);
    const int t = threadIdx.x;
    const int lane = t & 31, warp = t >> 5;
    const int wn = warp & 7, wm = warp >> 3;
    const __half* gA = &g_Ah[blockIdx.x * 64][0];

    float d[2][8][4];
#pragma unroll
    for (int mf = 0; mf < 2; mf++)
#pragma unroll
        for (int nf = 0; nf < 8; nf++)
#pragma unroll
            for (int k = 0; k < 4; k++) d[mf][nf][k] = 0.f;

    stage_copy(sb, 0, 0, t, gA);
    stage_copy(sb, 1, 1, t, gA);

    for (int c = 0; c < 12; c++) {
        if (c < 11) cp_wait1(); else cp_wait0();
        __syncthreads();

        const uint32_t stg = sb + (uint32_t)(c & 1) * STAGE;
        const uint32_t aB = stg + ((wm * 32 + (lane & 15)) * 72 + (lane >> 4) * 8) * 2;
        const uint32_t bB = stg + 9216 +
            ((wn * 64 + (lane & 7) + ((lane >> 3) & 1) * 8) * 72 + (lane >> 4) * 8) * 2;
#pragma unroll
        for (int ks = 0; ks < 4; ks++) {
            const uint32_t ko = ks * 32;
            uint32_t a[2][4], bf[4][4];
            LDSM4(a[0], aB + ko);
            LDSM4(a[1], aB + 16 * 144 + ko);
#pragma unroll
            for (int q = 0; q < 4; q++) LDSM4(bf[q], bB + q * 16 * 144 + ko);
#pragma unroll
            for (int mf = 0; mf < 2; mf++)
#pragma unroll
                for (int nf = 0; nf < 8; nf++) {
                    const uint32_t b0 = bf[nf >> 1][(nf & 1) ? 1 : 0];
                    const uint32_t b1 = bf[nf >> 1][(nf & 1) ? 3 : 2];
                    MMA16816(d[mf][nf], a[mf], b0, b1);
                }
        }
        __syncthreads();
        if (c + 2 < 12) stage_copy(sb, c + 2, c & 1, t, gA);
    }

    // ---- epilogue: p = re^2 + im^2; subset sums ----
    float Tacc[4] = {0, 0, 0, 0};
    float Bacc[4][5] = {};
#pragma unroll
    for (int mf = 0; mf < 2; mf++)
#pragma unroll
        for (int nf = 0; nf < 8; nf++) {
            const int i = wn * 32 + nf * 4 + (lane & 3);
#pragma unroll
            for (int hh = 0; hh < 2; hh++) {
                const float re = d[mf][nf][hh * 2];
                const float im = d[mf][nf][hh * 2 + 1];
                const float p = fmaf(re, re, im * im);
                const int slot = mf * 2 + hh;
                Tacc[slot] += p;
                if (i & 16) Bacc[slot][0] += p;
                if (i & 8)  Bacc[slot][1] += p;
                if (i & 4)  Bacc[slot][2] += p;
                if (i & 2)  Bacc[slot][3] += p;
                if (i & 1)  Bacc[slot][4] += p;
            }
        }
#pragma unroll
    for (int off = 1; off <= 2; off <<= 1) {
#pragma unroll
        for (int s = 0; s < 4; s++) {
            Tacc[s] += __shfl_xor_sync(0xffffffffu, Tacc[s], off);
#pragma unroll
            for (int k = 0; k < 5; k++)
                Bacc[s][k] += __shfl_xor_sync(0xffffffffu, Bacc[s][k], off);
        }
    }

    __syncthreads();                       // stage buffers now dead; alias
    float* sP = (float*)smem;              // [8 wn][64 row][8]
    if ((lane & 3) == 0) {
        const int g = lane >> 2;
#pragma unroll
        for (int s = 0; s < 4; s++) {
            const int row = wm * 32 + (s >> 1) * 16 + (s & 1) * 8 + g;
            float* pp = sP + (wn * 64 + row) * 8;
            pp[0] = Tacc[s];
            pp[1] = Bacc[s][0]; pp[2] = Bacc[s][1]; pp[3] = Bacc[s][2];
            pp[4] = Bacc[s][3]; pp[5] = Bacc[s][4];
        }
    }
    __syncthreads();

    {
        const int row = t >> 3, w = t & 7;
        float Z;
        if (w < 3) {
            Z = 0.f;
#pragma unroll
            for (int q = 0; q < 8; q++) {
                const float Tn = sP[(q * 64 + row) * 8];
                Z += ((q >> (2 - w)) & 1) ? -Tn : Tn;
            }
        } else {
            float sT = 0.f, sB = 0.f;
#pragma unroll
            for (int q = 0; q < 8; q++) {
                sT += sP[(q * 64 + row) * 8];
                sB += sP[(q * 64 + row) * 8 + (w - 2)];
            }
            Z = sT - 2.f * sB;
        }
        out[((size_t)blockIdx.x * 64 + row) * 8 + w] = Z;
    }
}

// ===================== launch ================================================
extern "C" void kernel_launch(void* const* d_in, const int* in_sizes, int n_in,
                              void* d_out, int out_size) {
    (void)in_sizes; (void)n_in; (void)out_size;
    const float* x     = (const float*)d_in[0];
    const float* W     = (const float*)d_in[1];
    const float* bvec  = (const float*)d_in[2];
    const float* scale = (const float*)d_in[3];
    const float* bias  = (const float*)d_in[4];
    const float* qw    = (const float*)d_in[5];
    float* out = (float*)d_out;

    cudaFuncSetAttribute(qc_main, cudaFuncAttributeMaxDynamicSharedMemorySize, QC_SMEM);

    build_unitary<<<256, 128>>>(qw);
    psi_kernel<<<1024, 256>>>(x, W, bvec, scale, bias);
    qc_main<<<128, 512, QC_SMEM>>>(out);
}